// round 1
// baseline (speedup 1.0000x reference)
#include <cuda_runtime.h>

// Problem constants
#define Bv   2
#define Sv   2048
#define Hv   1024
#define NHv  16
#define HDv  64
#define Mv   (Bv * Sv)          // 4096 rows in the flattened [B*S, H] view

// Scratch (device globals — no allocation allowed)
__device__ float g_q [Bv * Sv * Hv];
__device__ float g_k [Bv * Sv * Hv];
__device__ float g_v [Bv * Sv * Hv];
__device__ float g_ao[Bv * Sv * Hv];

__device__ __forceinline__ float elu1(float x) {
    return x > 0.f ? x + 1.f : __expf(x);
}

// ---------------------------------------------------------------------------
// C = A @ W^T,  A:[M,K] row-major, W:[N,K] row-major. M=4096, N=K=1024.
// 128x128 block tile, BK=8, 256 threads, 8x8 per-thread register tile.
// MODE 0: elu(x)+1 epilogue, write [B,NH,S,HD] layout  (q, k)
// MODE 1: identity epilogue,  write [B,NH,S,HD] layout  (v)
// MODE 2: identity epilogue,  write plain [M,N] row-major (final output)
// ---------------------------------------------------------------------------
template <int MODE>
__global__ __launch_bounds__(256) void gemm_nt(const float* __restrict__ A,
                                               const float* __restrict__ W,
                                               float* __restrict__ C)
{
    const int K = Hv;
    __shared__ float As[8][128];
    __shared__ float Ws[8][128];

    const int tid = threadIdx.x;
    const int m0  = blockIdx.y * 128;
    const int n0  = blockIdx.x * 128;
    const int tx  = tid & 15;       // 0..15 (col group)
    const int ty  = tid >> 4;       // 0..15 (row group)
    const int lr  = tid >> 1;       // 0..127: row within tile for loads
    const int lk  = (tid & 1) * 4;  // 0 or 4: k offset for loads

    const float* Ap = A + (size_t)(m0 + lr) * K + lk;
    const float* Wp = W + (size_t)(n0 + lr) * K + lk;

    float acc[8][8];
#pragma unroll
    for (int i = 0; i < 8; i++)
#pragma unroll
        for (int j = 0; j < 8; j++) acc[i][j] = 0.f;

    for (int k0 = 0; k0 < K; k0 += 8) {
        float4 av = *reinterpret_cast<const float4*>(Ap + k0);
        float4 wv = *reinterpret_cast<const float4*>(Wp + k0);
        __syncthreads();   // previous iteration's compute done before overwrite
        As[lk + 0][lr] = av.x; As[lk + 1][lr] = av.y;
        As[lk + 2][lr] = av.z; As[lk + 3][lr] = av.w;
        Ws[lk + 0][lr] = wv.x; Ws[lk + 1][lr] = wv.y;
        Ws[lk + 2][lr] = wv.z; Ws[lk + 3][lr] = wv.w;
        __syncthreads();
#pragma unroll
        for (int kk = 0; kk < 8; kk++) {
            float a[8], b[8];
            *reinterpret_cast<float4*>(&a[0]) = *reinterpret_cast<const float4*>(&As[kk][ty * 8]);
            *reinterpret_cast<float4*>(&a[4]) = *reinterpret_cast<const float4*>(&As[kk][ty * 8 + 4]);
            *reinterpret_cast<float4*>(&b[0]) = *reinterpret_cast<const float4*>(&Ws[kk][tx * 8]);
            *reinterpret_cast<float4*>(&b[4]) = *reinterpret_cast<const float4*>(&Ws[kk][tx * 8 + 4]);
#pragma unroll
            for (int i = 0; i < 8; i++)
#pragma unroll
                for (int j = 0; j < 8; j++)
                    acc[i][j] = fmaf(a[i], b[j], acc[i][j]);
        }
    }

#pragma unroll
    for (int i = 0; i < 8; i++) {
        const int m  = m0 + ty * 8 + i;
        const int bb = m >> 11;            // m / Sv
        const int ss = m & (Sv - 1);       // m % Sv
#pragma unroll
        for (int j = 0; j < 8; j++) {
            const int n = n0 + tx * 8 + j;
            float vv = acc[i][j];
            if (MODE == 0) vv = elu1(vv);
            if (MODE == 2) {
                C[(size_t)m * Hv + n] = vv;
            } else {
                const int hh = n >> 6, dd = n & 63;
                C[((size_t)(bb * NHv + hh) * Sv + ss) * HDv + dd] = vv;
            }
        }
    }
}

// ---------------------------------------------------------------------------
// Flash-style attention: one block = (b, h, 64-query chunk).
// Q/K stored d-major in smem (pitch 68 to keep float4 alignment + reduce
// conflicts), V key-major, P staged through smem for the PV GEMM.
// Online softmax (running max/sum) across 32 key tiles of 64.
// ---------------------------------------------------------------------------
#define QK_PITCH 68
#define ATTN_SMEM ((2 * 64 * QK_PITCH + 2 * 64 * 64) * 4 + 64 * 4)

__global__ __launch_bounds__(256) void attn_kernel(const float* __restrict__ q,
                                                   const float* __restrict__ k,
                                                   const float* __restrict__ v,
                                                   const int* __restrict__ mask,
                                                   float* __restrict__ out)
{
    extern __shared__ float sh[];
    float* Qs = sh;                          // [64][QK_PITCH]  Qs[d][row]
    float* Ks = sh + 64 * QK_PITCH;          // [64][QK_PITCH]  Ks[d][key]
    float* Vs = sh + 2 * 64 * QK_PITCH;      // [64][64]        Vs[key][d]
    float* Ps = Vs + 64 * 64;                // [64][64]        Ps[row][key]
    int*   Ms = (int*)(Ps + 64 * 64);        // [64]

    const int bb = blockIdx.z;
    const int hh = blockIdx.y;
    const int q0 = blockIdx.x * 64;

    const float* Qg = q + ((size_t)(bb * NHv + hh) * Sv + q0) * HDv;
    const float* Kg = k + (size_t)(bb * NHv + hh) * Sv * HDv;
    const float* Vg = v + (size_t)(bb * NHv + hh) * Sv * HDv;

    const int tid  = threadIdx.x;
    const int tx   = tid & 15;       // col group (4 cols)
    const int ty   = tid >> 4;       // row group (4 rows)
    const int lrow = tid >> 4;       // 0..15 base row for tile loads
    const int ld0  = (tid & 15) * 4; // 0..60 d offset for tile loads

    // Load Q tile transposed (d-major)
#pragma unroll
    for (int c = 0; c < 4; c++) {
        const int r = lrow + c * 16;
        float4 qv = *reinterpret_cast<const float4*>(Qg + r * HDv + ld0);
        Qs[(ld0 + 0) * QK_PITCH + r] = qv.x;
        Qs[(ld0 + 1) * QK_PITCH + r] = qv.y;
        Qs[(ld0 + 2) * QK_PITCH + r] = qv.z;
        Qs[(ld0 + 3) * QK_PITCH + r] = qv.w;
    }

    float o[4][4];
#pragma unroll
    for (int i = 0; i < 4; i++)
#pragma unroll
        for (int j = 0; j < 4; j++) o[i][j] = 0.f;
    float mrun[4], lrun[4];
#pragma unroll
    for (int i = 0; i < 4; i++) { mrun[i] = -1e30f; lrun[i] = 0.f; }

    for (int t = 0; t < Sv / 64; t++) {
        const int k0 = t * 64;
        __syncthreads();   // previous iteration's reads of Ks/Vs/Ps complete
        // Load K tile transposed + V tile natural
#pragma unroll
        for (int c = 0; c < 4; c++) {
            const int r = lrow + c * 16;
            float4 kv = *reinterpret_cast<const float4*>(Kg + (size_t)(k0 + r) * HDv + ld0);
            Ks[(ld0 + 0) * QK_PITCH + r] = kv.x;
            Ks[(ld0 + 1) * QK_PITCH + r] = kv.y;
            Ks[(ld0 + 2) * QK_PITCH + r] = kv.z;
            Ks[(ld0 + 3) * QK_PITCH + r] = kv.w;
            float4 vv = *reinterpret_cast<const float4*>(Vg + (size_t)(k0 + r) * HDv + ld0);
            *reinterpret_cast<float4*>(&Vs[r * 64 + ld0]) = vv;
        }
        if (tid < 64) Ms[tid] = mask[bb * Sv + k0 + tid];
        __syncthreads();

        // Scores: S = Q @ K^T over d (64)
        float s[4][4];
#pragma unroll
        for (int i = 0; i < 4; i++)
#pragma unroll
            for (int j = 0; j < 4; j++) s[i][j] = 0.f;
#pragma unroll 8
        for (int kk = 0; kk < 64; kk++) {
            float4 aq = *reinterpret_cast<const float4*>(&Qs[kk * QK_PITCH + ty * 4]);
            float4 bk = *reinterpret_cast<const float4*>(&Ks[kk * QK_PITCH + tx * 4]);
            const float a4[4] = {aq.x, aq.y, aq.z, aq.w};
            const float b4[4] = {bk.x, bk.y, bk.z, bk.w};
#pragma unroll
            for (int i = 0; i < 4; i++)
#pragma unroll
                for (int j = 0; j < 4; j++)
                    s[i][j] = fmaf(a4[i], b4[j], s[i][j]);
        }

        // Mask
#pragma unroll
        for (int j = 0; j < 4; j++) {
            if (Ms[tx * 4 + j] == 0) {
#pragma unroll
                for (int i = 0; i < 4; i++) s[i][j] = -1e30f;
            }
        }

        // Online softmax (row stats reduced across the 16 tx lanes)
#pragma unroll
        for (int i = 0; i < 4; i++) {
            float mx = fmaxf(fmaxf(s[i][0], s[i][1]), fmaxf(s[i][2], s[i][3]));
#pragma unroll
            for (int off = 8; off > 0; off >>= 1)
                mx = fmaxf(mx, __shfl_xor_sync(0xffffffffu, mx, off));
            const float mn    = fmaxf(mrun[i], mx);
            const float alpha = __expf(mrun[i] - mn);
            mrun[i] = mn;
            float rs = 0.f;
#pragma unroll
            for (int j = 0; j < 4; j++) {
                const float p = __expf(s[i][j] - mn);
                s[i][j] = p;
                rs += p;
            }
#pragma unroll
            for (int off = 8; off > 0; off >>= 1)
                rs += __shfl_xor_sync(0xffffffffu, rs, off);
            lrun[i] = lrun[i] * alpha + rs;
#pragma unroll
            for (int j = 0; j < 4; j++) o[i][j] *= alpha;
        }

        // Stage P through shared for the PV GEMM
#pragma unroll
        for (int i = 0; i < 4; i++)
            *reinterpret_cast<float4*>(&Ps[(ty * 4 + i) * 64 + tx * 4]) =
                make_float4(s[i][0], s[i][1], s[i][2], s[i][3]);
        __syncthreads();

        // O += P @ V
#pragma unroll 8
        for (int kk = 0; kk < 64; kk++) {
            float4 bv = *reinterpret_cast<const float4*>(&Vs[kk * 64 + tx * 4]);
#pragma unroll
            for (int i = 0; i < 4; i++) {
                const float a = Ps[(ty * 4 + i) * 64 + kk];
                o[i][0] = fmaf(a, bv.x, o[i][0]);
                o[i][1] = fmaf(a, bv.y, o[i][1]);
                o[i][2] = fmaf(a, bv.z, o[i][2]);
                o[i][3] = fmaf(a, bv.w, o[i][3]);
            }
        }
    }

    // Normalize and write to [B, S, H] layout (ready for the Wo GEMM)
#pragma unroll
    for (int i = 0; i < 4; i++) {
        const float inv  = 1.f / lrun[i];
        const int   srow = q0 + ty * 4 + i;
        float4 ov = make_float4(o[i][0] * inv, o[i][1] * inv, o[i][2] * inv, o[i][3] * inv);
        *reinterpret_cast<float4*>(&out[((size_t)bb * Sv + srow) * Hv + hh * 64 + tx * 4]) = ov;
    }
}

// ---------------------------------------------------------------------------
extern "C" void kernel_launch(void* const* d_in, const int* in_sizes, int n_in,
                              void* d_out, int out_size)
{
    const float* hs   = (const float*)d_in[0];
    const int*   mask = (const int*)d_in[1];
    const float* Wq   = (const float*)d_in[2];
    const float* Wk   = (const float*)d_in[3];
    const float* Wv   = (const float*)d_in[4];
    const float* Wo   = (const float*)d_in[5];
    float*       out  = (float*)d_out;

    float *qp, *kp, *vp, *aop;
    cudaGetSymbolAddress((void**)&qp,  g_q);
    cudaGetSymbolAddress((void**)&kp,  g_k);
    cudaGetSymbolAddress((void**)&vp,  g_v);
    cudaGetSymbolAddress((void**)&aop, g_ao);

    dim3 ggrid(Hv / 128, Mv / 128);   // (8, 32)
    gemm_nt<0><<<ggrid, 256>>>(hs, Wq, qp);
    gemm_nt<0><<<ggrid, 256>>>(hs, Wk, kp);
    gemm_nt<1><<<ggrid, 256>>>(hs, Wv, vp);

    cudaFuncSetAttribute(attn_kernel, cudaFuncAttributeMaxDynamicSharedMemorySize, ATTN_SMEM);
    attn_kernel<<<dim3(Sv / 64, NHv, Bv), 256, ATTN_SMEM>>>(qp, kp, vp, mask, aop);

    gemm_nt<2><<<ggrid, 256>>>(aop, Wo, out);
}

// round 3
// speedup vs baseline: 1.7973x; 1.7973x over previous
#include <cuda_runtime.h>
#include <cstdint>

// Problem constants
#define Bv   2
#define Sv   2048
#define Hv   1024
#define NHv  16
#define HDv  64
#define Mv   (Bv * Sv)

// Scratch (device globals — no allocation allowed)
__device__ float g_q [Bv * Sv * Hv];
__device__ float g_k [Bv * Sv * Hv];
__device__ float g_v [Bv * Sv * Hv];
__device__ float g_ao[Bv * Sv * Hv];

__device__ __forceinline__ float elu1(float x) {
    return x > 0.f ? x + 1.f : __expf(x);   // epilogue only: rare, fine on MUFU
}

// Fast exp: FMA/ALU only (no MUFU). x expected <= 0 (max-subtracted).
__device__ __forceinline__ float fexp(float x) {
    x = fmaxf(x, -80.f);
    float t  = x * 1.44269504089f;          // log2(e)
    float tb = t + 12582912.f;              // 2^23 + 2^22 magic: round to int
    float fi = tb - 12582912.f;
    float f  = t - fi;                      // f in [-0.5, 0.5]
    int   i  = __float_as_int(tb) - 0x4B400000;
    float p  = 1.33335581e-3f;
    p = fmaf(p, f, 9.61812910e-3f);
    p = fmaf(p, f, 5.55041087e-2f);
    p = fmaf(p, f, 2.40226507e-1f);
    p = fmaf(p, f, 6.93147181e-1f);
    p = fmaf(p, f, 1.0f);
    return __int_as_float(__float_as_int(p) + (i << 23));
}

// ---------------------------------------------------------------------------
// tf32 mma.sync helpers (legacy HMMA path — compiles at compute_103 baseline)
// ---------------------------------------------------------------------------
__device__ __forceinline__ uint32_t cvt_tf32(float x) {
    uint32_t r;
    asm("cvt.rna.tf32.f32 %0, %1;" : "=r"(r) : "f"(x));
    return r;
}
__device__ __forceinline__ void split_tf32(float x, uint32_t& hi, uint32_t& lo) {
    hi = cvt_tf32(x);
    lo = cvt_tf32(x - __uint_as_float(hi));
}
__device__ __forceinline__ void mma8(float* c, const uint32_t* a, uint32_t b0, uint32_t b1) {
    asm volatile(
        "mma.sync.aligned.m16n8k8.row.col.f32.tf32.tf32.f32 "
        "{%0,%1,%2,%3}, {%4,%5,%6,%7}, {%8,%9}, {%0,%1,%2,%3};"
        : "+f"(c[0]), "+f"(c[1]), "+f"(c[2]), "+f"(c[3])
        : "r"(a[0]), "r"(a[1]), "r"(a[2]), "r"(a[3]), "r"(b0), "r"(b1));
}

__device__ __forceinline__ uint32_t smem_u32(const void* p) {
    uint32_t a;
    asm("{ .reg .u64 t; cvta.to.shared.u64 t, %1; cvt.u32.u64 %0, t; }" : "=r"(a) : "l"(p));
    return a;
}
__device__ __forceinline__ void cp_async16(uint32_t sm, const void* g) {
    asm volatile("cp.async.cg.shared.global [%0], [%1], 16;" :: "r"(sm), "l"(g));
}
#define CP_COMMIT() asm volatile("cp.async.commit_group;" ::: "memory")
template <int N>
__device__ __forceinline__ void cp_wait() {
    asm volatile("cp.async.wait_group %0;" :: "n"(N) : "memory");
}

// ---------------------------------------------------------------------------
// GEMM: C = A @ W^T.  A:[M,K] row-major, W:[N,K] row-major, K=1024.
// BM=128 BN=128 BK=32, 3-stage cp.async, 256 thr, warp tile 32x64, tf32 mma.
// SPLIT: 3xTF32 (hi/lo) for fp32-class accuracy.
// MODE 0: elu+1 -> [B,NH,S,HD];  MODE 1: id -> [B,NH,S,HD];  MODE 2: id -> [M,N].
// ---------------------------------------------------------------------------
#define BM 128
#define BN 128
#define BK 32
#define LDT (BK + 4)                 // 36 floats pitch
#define STAGE_F (2 * BM * LDT)       // A tile + B tile
#define NSTAGE 3
#define GEMM_SMEM (NSTAGE * STAGE_F * 4)
#define NKC (Hv / BK)                // 32 chunks

template <int MODE, bool SPLIT>
__global__ __launch_bounds__(256) void gemm_mma(const float* __restrict__ A,
                                                const float* __restrict__ W,
                                                float* __restrict__ C)
{
    extern __shared__ float sm[];
    const int tid  = threadIdx.x;
    const int w    = tid >> 5;
    const int lane = tid & 31;
    const int g    = lane >> 2;
    const int t    = lane & 3;
    const int wm   = (w & 3) * 32;       // warp M offset (4 warps)
    const int wn   = (w >> 2) * 64;      // warp N offset (2 warps)
    const int m0   = blockIdx.y * BM;
    const int n0   = blockIdx.x * BN;

    const float* Ag = A + (size_t)m0 * Hv;
    const float* Wg = W + (size_t)n0 * Hv;

    auto load_stage = [&](int c, int s) {
        float* st = sm + s * STAGE_F;
        const int k0 = c * BK;
#pragma unroll
        for (int i = 0; i < 4; i++) {
            int idx = tid + i * 256;            // 0..1023
            int row = idx >> 3, seg = idx & 7;  // 8 segs of 4 floats
            cp_async16(smem_u32(st + row * LDT + seg * 4),
                       Ag + (size_t)row * Hv + k0 + seg * 4);
        }
#pragma unroll
        for (int i = 0; i < 4; i++) {
            int idx = tid + i * 256;
            int row = idx >> 3, seg = idx & 7;
            cp_async16(smem_u32(st + BM * LDT + row * LDT + seg * 4),
                       Wg + (size_t)row * Hv + k0 + seg * 4);
        }
    };

    float acc[2][8][4];
#pragma unroll
    for (int i = 0; i < 2; i++)
#pragma unroll
        for (int j = 0; j < 8; j++)
#pragma unroll
            for (int r = 0; r < 4; r++) acc[i][j][r] = 0.f;

    load_stage(0, 0); CP_COMMIT();
    load_stage(1, 1); CP_COMMIT();

    for (int c = 0; c < NKC; c++) {
        cp_wait<1>();          // chunk c resident
        __syncthreads();
        if (c + 2 < NKC) load_stage(c + 2, (c + 2) % NSTAGE);
        CP_COMMIT();

        const float* st = sm + (c % NSTAGE) * STAGE_F;
        const float* sA = st;
        const float* sB = st + BM * LDT;

#pragma unroll
        for (int ks = 0; ks < 4; ks++) {
            const int kk = ks * 8;
            uint32_t ah[2][4], al[2][4];
#pragma unroll
            for (int i = 0; i < 2; i++) {
                const int r = wm + i * 16 + g;
                float v0 = sA[r * LDT + kk + t];
                float v1 = sA[(r + 8) * LDT + kk + t];
                float v2 = sA[r * LDT + kk + t + 4];
                float v3 = sA[(r + 8) * LDT + kk + t + 4];
                if (SPLIT) {
                    split_tf32(v0, ah[i][0], al[i][0]);
                    split_tf32(v1, ah[i][1], al[i][1]);
                    split_tf32(v2, ah[i][2], al[i][2]);
                    split_tf32(v3, ah[i][3], al[i][3]);
                } else {
                    ah[i][0] = cvt_tf32(v0); ah[i][1] = cvt_tf32(v1);
                    ah[i][2] = cvt_tf32(v2); ah[i][3] = cvt_tf32(v3);
                }
            }
#pragma unroll
            for (int j = 0; j < 8; j++) {
                const int n = wn + j * 8 + g;
                float b0f = sB[n * LDT + kk + t];
                float b1f = sB[n * LDT + kk + t + 4];
                if (SPLIT) {
                    uint32_t b0h, b0l, b1h, b1l;
                    split_tf32(b0f, b0h, b0l);
                    split_tf32(b1f, b1h, b1l);
#pragma unroll
                    for (int i = 0; i < 2; i++) {
                        mma8(acc[i][j], al[i], b0h, b1h);
                        mma8(acc[i][j], ah[i], b0l, b1l);
                        mma8(acc[i][j], ah[i], b0h, b1h);
                    }
                } else {
                    uint32_t b0 = cvt_tf32(b0f), b1 = cvt_tf32(b1f);
#pragma unroll
                    for (int i = 0; i < 2; i++)
                        mma8(acc[i][j], ah[i], b0, b1);
                }
            }
        }
    }

    // epilogue
#pragma unroll
    for (int i = 0; i < 2; i++) {
#pragma unroll
        for (int rr = 0; rr < 2; rr++) {
            const int m  = m0 + wm + i * 16 + g + rr * 8;
            const int bb = m >> 11;
            const int ss = m & (Sv - 1);
#pragma unroll
            for (int j = 0; j < 8; j++) {
                float x0 = acc[i][j][rr * 2 + 0];
                float x1 = acc[i][j][rr * 2 + 1];
                if (MODE == 0) { x0 = elu1(x0); x1 = elu1(x1); }
                const int n = n0 + wn + j * 8 + 2 * t;
                float2 o2 = make_float2(x0, x1);
                if (MODE == 2) {
                    *reinterpret_cast<float2*>(&C[(size_t)m * Hv + n]) = o2;
                } else {
                    const int hh = n >> 6, dd = n & 63;
                    *reinterpret_cast<float2*>(
                        &C[((size_t)(bb * NHv + hh) * Sv + ss) * HDv + dd]) = o2;
                }
            }
        }
    }
}

// ---------------------------------------------------------------------------
// Flash attention with tf32 mma.sync.
// Block: 256 thr (8 warps), 128 queries; loop 64-key tiles.
// Scores: 3xTF32 (abs-accuracy critical: exp turns abs score err into rel
// weight err). PV: single tf32. P: acc->A frags via register shuffles.
// Softmax exp: fexp (FMA-only).
// ---------------------------------------------------------------------------
#define QP 68
#define VP 72
#define ATTN_SMEM ((128 * QP + 64 * QP + 64 * VP) * 4 + 64 * 4)

__global__ __launch_bounds__(256, 2) void attn_mma(const float* __restrict__ q,
                                                   const float* __restrict__ k,
                                                   const float* __restrict__ v,
                                                   const int* __restrict__ mask,
                                                   float* __restrict__ out)
{
    extern __shared__ float sh[];
    float* Qs = sh;                       // [128][QP]
    float* Ks = sh + 128 * QP;            // [64][QP]
    float* Vs = Ks + 64 * QP;             // [64][VP]
    int*   Ms = (int*)(Vs + 64 * VP);     // [64]

    const int bb = blockIdx.z;
    const int hh = blockIdx.y;
    const int q0 = blockIdx.x * 128;

    const float* Qg = q + ((size_t)(bb * NHv + hh) * Sv + q0) * HDv;
    const float* Kg = k + (size_t)(bb * NHv + hh) * Sv * HDv;
    const float* Vg = v + (size_t)(bb * NHv + hh) * Sv * HDv;

    const int tid  = threadIdx.x;
    const int w    = tid >> 5;
    const int lane = tid & 31;
    const int g    = lane >> 2;
    const int t    = lane & 3;
    const int qb   = w * 16;               // warp's query-row base

    // load Q tile (128x64) -> Qs
#pragma unroll
    for (int i = 0; i < 8; i++) {
        int idx = tid + i * 256;
        int row = idx >> 4, c4 = (idx & 15) * 4;
        float4 f = *reinterpret_cast<const float4*>(Qg + row * HDv + c4);
        *reinterpret_cast<float4*>(&Qs[row * QP + c4]) = f;
    }

    float oacc[8][4];
#pragma unroll
    for (int j = 0; j < 8; j++)
#pragma unroll
        for (int r = 0; r < 4; r++) oacc[j][r] = 0.f;
    float m0r = -1e30f, m1r = -1e30f, l0r = 0.f, l1r = 0.f;

    for (int tk = 0; tk < Sv / 64; tk++) {
        const int k0 = tk * 64;
        __syncthreads();
#pragma unroll
        for (int i = 0; i < 4; i++) {
            int idx = tid + i * 256;
            int row = idx >> 4, c4 = (idx & 15) * 4;
            float4 fk = *reinterpret_cast<const float4*>(Kg + (size_t)(k0 + row) * HDv + c4);
            *reinterpret_cast<float4*>(&Ks[row * QP + c4]) = fk;
            float4 fv = *reinterpret_cast<const float4*>(Vg + (size_t)(k0 + row) * HDv + c4);
            *reinterpret_cast<float4*>(&Vs[row * VP + c4]) = fv;
        }
        if (tid < 64) Ms[tid] = mask[bb * Sv + k0 + tid];
        __syncthreads();

        // ---- scores: S = Q @ K^T  (3xTF32) ----
        float sacc[8][4];
#pragma unroll
        for (int j = 0; j < 8; j++)
#pragma unroll
            for (int r = 0; r < 4; r++) sacc[j][r] = 0.f;

#pragma unroll
        for (int ks = 0; ks < 8; ks++) {
            const int kk = ks * 8;
            uint32_t ah[4], al[4];
            split_tf32(Qs[(qb + g) * QP + kk + t],          ah[0], al[0]);
            split_tf32(Qs[(qb + g + 8) * QP + kk + t],      ah[1], al[1]);
            split_tf32(Qs[(qb + g) * QP + kk + t + 4],      ah[2], al[2]);
            split_tf32(Qs[(qb + g + 8) * QP + kk + t + 4],  ah[3], al[3]);
#pragma unroll
            for (int j = 0; j < 8; j++) {
                uint32_t b0h, b0l, b1h, b1l;
                split_tf32(Ks[(j * 8 + g) * QP + kk + t],     b0h, b0l);
                split_tf32(Ks[(j * 8 + g) * QP + kk + t + 4], b1h, b1l);
                mma8(sacc[j], al, b0h, b1h);
                mma8(sacc[j], ah, b0l, b1l);
                mma8(sacc[j], ah, b0h, b1h);
            }
        }

        // ---- mask ----
#pragma unroll
        for (int j = 0; j < 8; j++) {
            if (Ms[j * 8 + 2 * t] == 0)     { sacc[j][0] = -1e30f; sacc[j][2] = -1e30f; }
            if (Ms[j * 8 + 2 * t + 1] == 0) { sacc[j][1] = -1e30f; sacc[j][3] = -1e30f; }
        }

        // ---- online softmax (rows g and g+8) ----
        float mx0 = -1e30f, mx1 = -1e30f;
#pragma unroll
        for (int j = 0; j < 8; j++) {
            mx0 = fmaxf(mx0, fmaxf(sacc[j][0], sacc[j][1]));
            mx1 = fmaxf(mx1, fmaxf(sacc[j][2], sacc[j][3]));
        }
        mx0 = fmaxf(mx0, __shfl_xor_sync(0xffffffffu, mx0, 1));
        mx0 = fmaxf(mx0, __shfl_xor_sync(0xffffffffu, mx0, 2));
        mx1 = fmaxf(mx1, __shfl_xor_sync(0xffffffffu, mx1, 1));
        mx1 = fmaxf(mx1, __shfl_xor_sync(0xffffffffu, mx1, 2));

        const float mn0 = fmaxf(m0r, mx0);
        const float mn1 = fmaxf(m1r, mx1);
        const float a0  = fexp(m0r - mn0);
        const float a1  = fexp(m1r - mn1);
        m0r = mn0; m1r = mn1;

        float s0 = 0.f, s1 = 0.f;
#pragma unroll
        for (int j = 0; j < 8; j++) {
            sacc[j][0] = fexp(sacc[j][0] - mn0);
            sacc[j][1] = fexp(sacc[j][1] - mn0);
            sacc[j][2] = fexp(sacc[j][2] - mn1);
            sacc[j][3] = fexp(sacc[j][3] - mn1);
            s0 += sacc[j][0] + sacc[j][1];
            s1 += sacc[j][2] + sacc[j][3];
        }
        s0 += __shfl_xor_sync(0xffffffffu, s0, 1);
        s0 += __shfl_xor_sync(0xffffffffu, s0, 2);
        s1 += __shfl_xor_sync(0xffffffffu, s1, 1);
        s1 += __shfl_xor_sync(0xffffffffu, s1, 2);
        l0r = l0r * a0 + s0;
        l1r = l1r * a1 + s1;
#pragma unroll
        for (int j = 0; j < 8; j++) {
            oacc[j][0] *= a0; oacc[j][1] *= a0;
            oacc[j][2] *= a1; oacc[j][3] *= a1;
        }

        // ---- O += P @ V (single tf32; P frags via shuffle) ----
        const int src0 = (lane & 28) | (t >> 1);
        const int src1 = src0 | 2;
        const bool odd = (t & 1) != 0;
#pragma unroll
        for (int ks = 0; ks < 8; ks++) {
            float p0 = sacc[ks][0], p1 = sacc[ks][1];
            float p2 = sacc[ks][2], p3 = sacc[ks][3];
            float x0 = __shfl_sync(0xffffffffu, p0, src0);
            float x1 = __shfl_sync(0xffffffffu, p1, src0);
            float z0 = __shfl_sync(0xffffffffu, p2, src0);
            float z1 = __shfl_sync(0xffffffffu, p3, src0);
            float y0 = __shfl_sync(0xffffffffu, p0, src1);
            float y1 = __shfl_sync(0xffffffffu, p1, src1);
            float w0 = __shfl_sync(0xffffffffu, p2, src1);
            float w1 = __shfl_sync(0xffffffffu, p3, src1);
            uint32_t ap[4];
            ap[0] = cvt_tf32(odd ? x1 : x0);    // P[g   ][8ks+t]
            ap[1] = cvt_tf32(odd ? z1 : z0);    // P[g+8 ][8ks+t]
            ap[2] = cvt_tf32(odd ? y1 : y0);    // P[g   ][8ks+t+4]
            ap[3] = cvt_tf32(odd ? w1 : w0);    // P[g+8 ][8ks+t+4]
#pragma unroll
            for (int j = 0; j < 8; j++) {
                uint32_t b0 = cvt_tf32(Vs[(ks * 8 + t) * VP + j * 8 + g]);
                uint32_t b1 = cvt_tf32(Vs[(ks * 8 + t + 4) * VP + j * 8 + g]);
                mma8(oacc[j], ap, b0, b1);
            }
        }
    }

    // ---- normalize + write [B,S,H] ----
    const float i0 = 1.f / l0r;
    const float i1 = 1.f / l1r;
    const int r0 = q0 + qb + g;
    const int r1 = r0 + 8;
#pragma unroll
    for (int j = 0; j < 8; j++) {
        const int col = hh * 64 + j * 8 + 2 * t;
        *reinterpret_cast<float2*>(&out[((size_t)bb * Sv + r0) * Hv + col]) =
            make_float2(oacc[j][0] * i0, oacc[j][1] * i0);
        *reinterpret_cast<float2*>(&out[((size_t)bb * Sv + r1) * Hv + col]) =
            make_float2(oacc[j][2] * i1, oacc[j][3] * i1);
    }
}

// ---------------------------------------------------------------------------
extern "C" void kernel_launch(void* const* d_in, const int* in_sizes, int n_in,
                              void* d_out, int out_size)
{
    const float* hs   = (const float*)d_in[0];
    const int*   mask = (const int*)d_in[1];
    const float* Wq   = (const float*)d_in[2];
    const float* Wk   = (const float*)d_in[3];
    const float* Wv   = (const float*)d_in[4];
    const float* Wo   = (const float*)d_in[5];
    float*       out  = (float*)d_out;

    float *qp, *kp, *vp, *aop;
    cudaGetSymbolAddress((void**)&qp,  g_q);
    cudaGetSymbolAddress((void**)&kp,  g_k);
    cudaGetSymbolAddress((void**)&vp,  g_v);
    cudaGetSymbolAddress((void**)&aop, g_ao);

    cudaFuncSetAttribute(gemm_mma<0, true>,  cudaFuncAttributeMaxDynamicSharedMemorySize, GEMM_SMEM);
    cudaFuncSetAttribute(gemm_mma<1, false>, cudaFuncAttributeMaxDynamicSharedMemorySize, GEMM_SMEM);
    cudaFuncSetAttribute(gemm_mma<2, false>, cudaFuncAttributeMaxDynamicSharedMemorySize, GEMM_SMEM);
    cudaFuncSetAttribute(attn_mma, cudaFuncAttributeMaxDynamicSharedMemorySize, ATTN_SMEM);

    dim3 ggrid(Hv / BN, Mv / BM);   // (8, 32)
    gemm_mma<0, true><<<ggrid, 256, GEMM_SMEM>>>(hs, Wq, qp);
    gemm_mma<0, true><<<ggrid, 256, GEMM_SMEM>>>(hs, Wk, kp);
    gemm_mma<1, false><<<ggrid, 256, GEMM_SMEM>>>(hs, Wv, vp);

    attn_mma<<<dim3(Sv / 128, NHv, Bv), 256, ATTN_SMEM>>>(qp, kp, vp, mask, aop);

    gemm_mma<2, false><<<ggrid, 256, GEMM_SMEM>>>(aop, Wo, out);
}

// round 4
// speedup vs baseline: 1.9814x; 1.1024x over previous
#include <cuda_runtime.h>
#include <cstdint>

// Problem constants
#define Bv   2
#define Sv   2048
#define Hv   1024
#define NHv  16
#define HDv  64
#define Mv   (Bv * Sv)

// Scratch (device globals — no allocation allowed)
__device__ float g_q [Bv * Sv * Hv];
__device__ float g_k [Bv * Sv * Hv];
__device__ float g_v [Bv * Sv * Hv];
__device__ float g_ao[Bv * Sv * Hv];

__device__ __forceinline__ float elu1(float x) {
    return x > 0.f ? x + 1.f : __expf(x);
}

// Fast exp: FMA/ALU only (no MUFU). x expected <= 0 (max-subtracted).
__device__ __forceinline__ float fexp(float x) {
    x = fmaxf(x, -80.f);
    float t  = x * 1.44269504089f;
    float tb = t + 12582912.f;
    float fi = tb - 12582912.f;
    float f  = t - fi;
    int   i  = __float_as_int(tb) - 0x4B400000;
    float p  = 1.33335581e-3f;
    p = fmaf(p, f, 9.61812910e-3f);
    p = fmaf(p, f, 5.55041087e-2f);
    p = fmaf(p, f, 2.40226507e-1f);
    p = fmaf(p, f, 6.93147181e-1f);
    p = fmaf(p, f, 1.0f);
    return __int_as_float(__float_as_int(p) + (i << 23));
}

// ---------------------------------------------------------------------------
// tf32 mma.sync helpers
// ---------------------------------------------------------------------------
__device__ __forceinline__ uint32_t cvt_tf32(float x) {
    uint32_t r;
    asm("cvt.rna.tf32.f32 %0, %1;" : "=r"(r) : "f"(x));
    return r;
}
__device__ __forceinline__ void split_tf32(float x, uint32_t& hi, uint32_t& lo) {
    hi = cvt_tf32(x);
    lo = cvt_tf32(x - __uint_as_float(hi));
}
__device__ __forceinline__ void mma8(float* c, const uint32_t* a, uint32_t b0, uint32_t b1) {
    asm volatile(
        "mma.sync.aligned.m16n8k8.row.col.f32.tf32.tf32.f32 "
        "{%0,%1,%2,%3}, {%4,%5,%6,%7}, {%8,%9}, {%0,%1,%2,%3};"
        : "+f"(c[0]), "+f"(c[1]), "+f"(c[2]), "+f"(c[3])
        : "r"(a[0]), "r"(a[1]), "r"(a[2]), "r"(a[3]), "r"(b0), "r"(b1));
}

__device__ __forceinline__ uint32_t smem_u32(const void* p) {
    uint32_t a;
    asm("{ .reg .u64 t; cvta.to.shared.u64 t, %1; cvt.u32.u64 %0, t; }" : "=r"(a) : "l"(p));
    return a;
}
__device__ __forceinline__ void cp_async16(uint32_t sm, const void* g) {
    asm volatile("cp.async.cg.shared.global [%0], [%1], 16;" :: "r"(sm), "l"(g));
}
#define CP_COMMIT() asm volatile("cp.async.commit_group;" ::: "memory")
template <int N>
__device__ __forceinline__ void cp_wait() {
    asm volatile("cp.async.wait_group %0;" :: "n"(N) : "memory");
}

// ---------------------------------------------------------------------------
// GEMM body: C = A @ W^T.  Tile 128x128x32, 3-stage cp.async, tf32 mma.
// ---------------------------------------------------------------------------
#define BM 128
#define BN 128
#define BK 32
#define LDT (BK + 4)
#define STAGE_F (2 * BM * LDT)
#define NSTAGE 3
#define GEMM_SMEM (NSTAGE * STAGE_F * 4)
#define NKC (Hv / BK)

// OUT_LAYOUT: 0 -> [B,NH,S,HD], 1 -> [M,N] row-major
template <int OUT_LAYOUT>
__device__ __forceinline__ void gemm_body(const float* __restrict__ A,
                                          const float* __restrict__ W,
                                          float* __restrict__ C,
                                          bool split, bool do_elu,
                                          float* sm, int m0, int n0)
{
    const int tid  = threadIdx.x;
    const int w    = tid >> 5;
    const int lane = tid & 31;
    const int g    = lane >> 2;
    const int t    = lane & 3;
    const int wm   = (w & 3) * 32;
    const int wn   = (w >> 2) * 64;

    const float* Ag = A + (size_t)m0 * Hv;
    const float* Wg = W + (size_t)n0 * Hv;

    auto load_stage = [&](int c, int s) {
        float* st = sm + s * STAGE_F;
        const int k0 = c * BK;
#pragma unroll
        for (int i = 0; i < 4; i++) {
            int idx = tid + i * 256;
            int row = idx >> 3, seg = idx & 7;
            cp_async16(smem_u32(st + row * LDT + seg * 4),
                       Ag + (size_t)row * Hv + k0 + seg * 4);
        }
#pragma unroll
        for (int i = 0; i < 4; i++) {
            int idx = tid + i * 256;
            int row = idx >> 3, seg = idx & 7;
            cp_async16(smem_u32(st + BM * LDT + row * LDT + seg * 4),
                       Wg + (size_t)row * Hv + k0 + seg * 4);
        }
    };

    float acc[2][8][4];
#pragma unroll
    for (int i = 0; i < 2; i++)
#pragma unroll
        for (int j = 0; j < 8; j++)
#pragma unroll
            for (int r = 0; r < 4; r++) acc[i][j][r] = 0.f;

    load_stage(0, 0); CP_COMMIT();
    load_stage(1, 1); CP_COMMIT();

    for (int c = 0; c < NKC; c++) {
        cp_wait<1>();
        __syncthreads();
        if (c + 2 < NKC) load_stage(c + 2, (c + 2) % NSTAGE);
        CP_COMMIT();

        const float* st = sm + (c % NSTAGE) * STAGE_F;
        const float* sA = st;
        const float* sB = st + BM * LDT;

#pragma unroll
        for (int ks = 0; ks < 4; ks++) {
            const int kk = ks * 8;
            uint32_t ah[2][4], al[2][4];
#pragma unroll
            for (int i = 0; i < 2; i++) {
                const int r = wm + i * 16 + g;
                float v0 = sA[r * LDT + kk + t];
                float v1 = sA[(r + 8) * LDT + kk + t];
                float v2 = sA[r * LDT + kk + t + 4];
                float v3 = sA[(r + 8) * LDT + kk + t + 4];
                if (split) {
                    split_tf32(v0, ah[i][0], al[i][0]);
                    split_tf32(v1, ah[i][1], al[i][1]);
                    split_tf32(v2, ah[i][2], al[i][2]);
                    split_tf32(v3, ah[i][3], al[i][3]);
                } else {
                    ah[i][0] = cvt_tf32(v0); ah[i][1] = cvt_tf32(v1);
                    ah[i][2] = cvt_tf32(v2); ah[i][3] = cvt_tf32(v3);
                }
            }
#pragma unroll
            for (int j = 0; j < 8; j++) {
                const int n = wn + j * 8 + g;
                float b0f = sB[n * LDT + kk + t];
                float b1f = sB[n * LDT + kk + t + 4];
                if (split) {
                    uint32_t b0h, b0l, b1h, b1l;
                    split_tf32(b0f, b0h, b0l);
                    split_tf32(b1f, b1h, b1l);
#pragma unroll
                    for (int i = 0; i < 2; i++) {
                        mma8(acc[i][j], al[i], b0h, b1h);
                        mma8(acc[i][j], ah[i], b0l, b1l);
                        mma8(acc[i][j], ah[i], b0h, b1h);
                    }
                } else {
                    uint32_t b0 = cvt_tf32(b0f), b1 = cvt_tf32(b1f);
#pragma unroll
                    for (int i = 0; i < 2; i++)
                        mma8(acc[i][j], ah[i], b0, b1);
                }
            }
        }
    }

#pragma unroll
    for (int i = 0; i < 2; i++) {
#pragma unroll
        for (int rr = 0; rr < 2; rr++) {
            const int m  = m0 + wm + i * 16 + g + rr * 8;
            const int bb = m >> 11;
            const int ss = m & (Sv - 1);
#pragma unroll
            for (int j = 0; j < 8; j++) {
                float x0 = acc[i][j][rr * 2 + 0];
                float x1 = acc[i][j][rr * 2 + 1];
                if (do_elu) { x0 = elu1(x0); x1 = elu1(x1); }
                const int n = n0 + wn + j * 8 + 2 * t;
                float2 o2 = make_float2(x0, x1);
                if (OUT_LAYOUT == 1) {
                    *reinterpret_cast<float2*>(&C[(size_t)m * Hv + n]) = o2;
                } else {
                    const int hh = n >> 6, dd = n & 63;
                    *reinterpret_cast<float2*>(
                        &C[((size_t)(bb * NHv + hh) * Sv + ss) * HDv + dd]) = o2;
                }
            }
        }
    }
}

// Fused Q/K/V projection: blockIdx.z selects weight/output/flags.
__global__ __launch_bounds__(256) void proj_qkv(const float* __restrict__ A,
                                                const float* __restrict__ Wq,
                                                const float* __restrict__ Wk,
                                                const float* __restrict__ Wv,
                                                float* __restrict__ q,
                                                float* __restrict__ k,
                                                float* __restrict__ v)
{
    extern __shared__ float sm[];
    const int z = blockIdx.z;
    const float* W = (z == 0) ? Wq : (z == 1) ? Wk : Wv;
    float*       C = (z == 0) ? q  : (z == 1) ? k  : v;
    const bool split  = (z < 2);
    const bool do_elu = (z < 2);
    gemm_body<0>(A, W, C, split, do_elu, sm, blockIdx.y * BM, blockIdx.x * BN);
}

// Output projection (single tf32, row-major out)
__global__ __launch_bounds__(256) void proj_o(const float* __restrict__ A,
                                              const float* __restrict__ Wo,
                                              float* __restrict__ C)
{
    extern __shared__ float sm[];
    gemm_body<1>(A, Wo, C, false, false, sm, blockIdx.y * BM, blockIdx.x * BN);
}

// ---------------------------------------------------------------------------
// Flash attention, tf32 mma. Conversions hoisted out of inner loops:
// K pre-split to Khi/Klo and V pre-converted to tf32 at tile-load time.
// Q kept fp32 in smem, split per-ks (32 splits/lane/tile).
// ---------------------------------------------------------------------------
#define QP 68
#define VP 72
// Qs fp32[128][QP] + Khi u32[64][QP] + Klo u32[64][QP] + Vtf u32[64][VP] + mask
#define ATTN_SMEM ((128 * QP + 64 * QP + 64 * QP + 64 * VP) * 4 + 64 * 4)

__global__ __launch_bounds__(256, 2) void attn_mma(const float* __restrict__ q,
                                                   const float* __restrict__ k,
                                                   const float* __restrict__ v,
                                                   const int* __restrict__ mask,
                                                   float* __restrict__ out)
{
    extern __shared__ float sh[];
    float*    Qs  = sh;                                  // [128][QP] fp32
    uint32_t* Khi = (uint32_t*)(sh + 128 * QP);          // [64][QP]
    uint32_t* Klo = Khi + 64 * QP;                       // [64][QP]
    uint32_t* Vtf = Klo + 64 * QP;                       // [64][VP]
    int*      Ms  = (int*)(Vtf + 64 * VP);               // [64]

    const int bb = blockIdx.z;
    const int hh = blockIdx.y;
    const int q0 = blockIdx.x * 128;

    const float* Qg = q + ((size_t)(bb * NHv + hh) * Sv + q0) * HDv;
    const float* Kg = k + (size_t)(bb * NHv + hh) * Sv * HDv;
    const float* Vg = v + (size_t)(bb * NHv + hh) * Sv * HDv;

    const int tid  = threadIdx.x;
    const int w    = tid >> 5;
    const int lane = tid & 31;
    const int g    = lane >> 2;
    const int t    = lane & 3;
    const int qb   = w * 16;

    // load Q tile (128x64) -> Qs (fp32)
#pragma unroll
    for (int i = 0; i < 8; i++) {
        int idx = tid + i * 256;
        int row = idx >> 4, c4 = (idx & 15) * 4;
        float4 f = *reinterpret_cast<const float4*>(Qg + row * HDv + c4);
        *reinterpret_cast<float4*>(&Qs[row * QP + c4]) = f;
    }

    float oacc[8][4];
#pragma unroll
    for (int j = 0; j < 8; j++)
#pragma unroll
        for (int r = 0; r < 4; r++) oacc[j][r] = 0.f;
    float m0r = -1e30f, m1r = -1e30f, l0r = 0.f, l1r = 0.f;

    for (int tk = 0; tk < Sv / 64; tk++) {
        const int k0 = tk * 64;
        __syncthreads();
        // ---- tile load: K split -> Khi/Klo, V cvt -> Vtf ----
#pragma unroll
        for (int i = 0; i < 4; i++) {
            int idx = tid + i * 256;
            int row = idx >> 4, c4 = (idx & 15) * 4;
            float4 fk = *reinterpret_cast<const float4*>(Kg + (size_t)(k0 + row) * HDv + c4);
            uint4 h, l;
            split_tf32(fk.x, h.x, l.x);
            split_tf32(fk.y, h.y, l.y);
            split_tf32(fk.z, h.z, l.z);
            split_tf32(fk.w, h.w, l.w);
            *reinterpret_cast<uint4*>(&Khi[row * QP + c4]) = h;
            *reinterpret_cast<uint4*>(&Klo[row * QP + c4]) = l;
            float4 fv = *reinterpret_cast<const float4*>(Vg + (size_t)(k0 + row) * HDv + c4);
            uint4 vt;
            vt.x = cvt_tf32(fv.x); vt.y = cvt_tf32(fv.y);
            vt.z = cvt_tf32(fv.z); vt.w = cvt_tf32(fv.w);
            *reinterpret_cast<uint4*>(&Vtf[row * VP + c4]) = vt;
        }
        if (tid < 64) Ms[tid] = mask[bb * Sv + k0 + tid];
        __syncthreads();

        // ---- scores: S = Q @ K^T  (3xTF32, pure lds+mma inner loop) ----
        float sacc[8][4];
#pragma unroll
        for (int j = 0; j < 8; j++)
#pragma unroll
            for (int r = 0; r < 4; r++) sacc[j][r] = 0.f;

#pragma unroll
        for (int ks = 0; ks < 8; ks++) {
            const int kk = ks * 8;
            uint32_t ah[4], al[4];
            split_tf32(Qs[(qb + g) * QP + kk + t],          ah[0], al[0]);
            split_tf32(Qs[(qb + g + 8) * QP + kk + t],      ah[1], al[1]);
            split_tf32(Qs[(qb + g) * QP + kk + t + 4],      ah[2], al[2]);
            split_tf32(Qs[(qb + g + 8) * QP + kk + t + 4],  ah[3], al[3]);
#pragma unroll
            for (int j = 0; j < 8; j++) {
                const int kr = (j * 8 + g) * QP + kk + t;
                uint32_t b0h = Khi[kr], b1h = Khi[kr + 4];
                uint32_t b0l = Klo[kr], b1l = Klo[kr + 4];
                mma8(sacc[j], al, b0h, b1h);
                mma8(sacc[j], ah, b0l, b1l);
                mma8(sacc[j], ah, b0h, b1h);
            }
        }

        // ---- mask ----
#pragma unroll
        for (int j = 0; j < 8; j++) {
            if (Ms[j * 8 + 2 * t] == 0)     { sacc[j][0] = -1e30f; sacc[j][2] = -1e30f; }
            if (Ms[j * 8 + 2 * t + 1] == 0) { sacc[j][1] = -1e30f; sacc[j][3] = -1e30f; }
        }

        // ---- online softmax ----
        float mx0 = -1e30f, mx1 = -1e30f;
#pragma unroll
        for (int j = 0; j < 8; j++) {
            mx0 = fmaxf(mx0, fmaxf(sacc[j][0], sacc[j][1]));
            mx1 = fmaxf(mx1, fmaxf(sacc[j][2], sacc[j][3]));
        }
        mx0 = fmaxf(mx0, __shfl_xor_sync(0xffffffffu, mx0, 1));
        mx0 = fmaxf(mx0, __shfl_xor_sync(0xffffffffu, mx0, 2));
        mx1 = fmaxf(mx1, __shfl_xor_sync(0xffffffffu, mx1, 1));
        mx1 = fmaxf(mx1, __shfl_xor_sync(0xffffffffu, mx1, 2));

        const float mn0 = fmaxf(m0r, mx0);
        const float mn1 = fmaxf(m1r, mx1);
        const float a0  = fexp(m0r - mn0);
        const float a1  = fexp(m1r - mn1);
        m0r = mn0; m1r = mn1;

        float s0 = 0.f, s1 = 0.f;
#pragma unroll
        for (int j = 0; j < 8; j++) {
            sacc[j][0] = fexp(sacc[j][0] - mn0);
            sacc[j][1] = fexp(sacc[j][1] - mn0);
            sacc[j][2] = fexp(sacc[j][2] - mn1);
            sacc[j][3] = fexp(sacc[j][3] - mn1);
            s0 += sacc[j][0] + sacc[j][1];
            s1 += sacc[j][2] + sacc[j][3];
        }
        s0 += __shfl_xor_sync(0xffffffffu, s0, 1);
        s0 += __shfl_xor_sync(0xffffffffu, s0, 2);
        s1 += __shfl_xor_sync(0xffffffffu, s1, 1);
        s1 += __shfl_xor_sync(0xffffffffu, s1, 2);
        l0r = l0r * a0 + s0;
        l1r = l1r * a1 + s1;
#pragma unroll
        for (int j = 0; j < 8; j++) {
            oacc[j][0] *= a0; oacc[j][1] *= a0;
            oacc[j][2] *= a1; oacc[j][3] *= a1;
        }

        // ---- O += P @ V (single tf32; P frags via shuffle) ----
        const int src0 = (lane & 28) | (t >> 1);
        const int src1 = src0 | 2;
        const bool odd = (t & 1) != 0;
#pragma unroll
        for (int ks = 0; ks < 8; ks++) {
            float p0 = sacc[ks][0], p1 = sacc[ks][1];
            float p2 = sacc[ks][2], p3 = sacc[ks][3];
            float x0 = __shfl_sync(0xffffffffu, p0, src0);
            float x1 = __shfl_sync(0xffffffffu, p1, src0);
            float z0 = __shfl_sync(0xffffffffu, p2, src0);
            float z1 = __shfl_sync(0xffffffffu, p3, src0);
            float y0 = __shfl_sync(0xffffffffu, p0, src1);
            float y1 = __shfl_sync(0xffffffffu, p1, src1);
            float w0 = __shfl_sync(0xffffffffu, p2, src1);
            float w1 = __shfl_sync(0xffffffffu, p3, src1);
            uint32_t ap[4];
            ap[0] = cvt_tf32(odd ? x1 : x0);
            ap[1] = cvt_tf32(odd ? z1 : z0);
            ap[2] = cvt_tf32(odd ? y1 : y0);
            ap[3] = cvt_tf32(odd ? w1 : w0);
#pragma unroll
            for (int j = 0; j < 8; j++) {
                uint32_t b0 = Vtf[(ks * 8 + t) * VP + j * 8 + g];
                uint32_t b1 = Vtf[(ks * 8 + t + 4) * VP + j * 8 + g];
                mma8(oacc[j], ap, b0, b1);
            }
        }
    }

    // ---- normalize + write [B,S,H] ----
    const float i0 = 1.f / l0r;
    const float i1 = 1.f / l1r;
    const int r0 = q0 + qb + g;
    const int r1 = r0 + 8;
#pragma unroll
    for (int j = 0; j < 8; j++) {
        const int col = hh * 64 + j * 8 + 2 * t;
        *reinterpret_cast<float2*>(&out[((size_t)bb * Sv + r0) * Hv + col]) =
            make_float2(oacc[j][0] * i0, oacc[j][1] * i0);
        *reinterpret_cast<float2*>(&out[((size_t)bb * Sv + r1) * Hv + col]) =
            make_float2(oacc[j][2] * i1, oacc[j][3] * i1);
    }
}

// ---------------------------------------------------------------------------
extern "C" void kernel_launch(void* const* d_in, const int* in_sizes, int n_in,
                              void* d_out, int out_size)
{
    const float* hs   = (const float*)d_in[0];
    const int*   mask = (const int*)d_in[1];
    const float* Wq   = (const float*)d_in[2];
    const float* Wk   = (const float*)d_in[3];
    const float* Wv   = (const float*)d_in[4];
    const float* Wo   = (const float*)d_in[5];
    float*       out  = (float*)d_out;

    float *qp, *kp, *vp, *aop;
    cudaGetSymbolAddress((void**)&qp,  g_q);
    cudaGetSymbolAddress((void**)&kp,  g_k);
    cudaGetSymbolAddress((void**)&vp,  g_v);
    cudaGetSymbolAddress((void**)&aop, g_ao);

    cudaFuncSetAttribute(proj_qkv, cudaFuncAttributeMaxDynamicSharedMemorySize, GEMM_SMEM);
    cudaFuncSetAttribute(proj_o,   cudaFuncAttributeMaxDynamicSharedMemorySize, GEMM_SMEM);
    cudaFuncSetAttribute(attn_mma, cudaFuncAttributeMaxDynamicSharedMemorySize, ATTN_SMEM);

    proj_qkv<<<dim3(Hv / BN, Mv / BM, 3), 256, GEMM_SMEM>>>(hs, Wq, Wk, Wv, qp, kp, vp);

    attn_mma<<<dim3(Sv / 128, NHv, Bv), 256, ATTN_SMEM>>>(qp, kp, vp, mask, aop);

    proj_o<<<dim3(Hv / BN, Mv / BM), 256, GEMM_SMEM>>>(aop, Wo, out);
}

// round 5
// speedup vs baseline: 2.5831x; 1.3036x over previous
#include <cuda_runtime.h>
#include <cuda_bf16.h>
#include <cstdint>

// Problem constants
#define Bv   2
#define Sv   2048
#define Hv   1024
#define NHv  16
#define HDv  64
#define Mv   (Bv * Sv)

// Scratch (device globals — no allocation allowed)
__device__ __nv_bfloat16 g_ahi[Mv * Hv], g_alo[Mv * Hv];
__device__ __nv_bfloat16 g_wqhi[Hv * Hv], g_wqlo[Hv * Hv];
__device__ __nv_bfloat16 g_wkhi[Hv * Hv], g_wklo[Hv * Hv];
__device__ __nv_bfloat16 g_wvhi[Hv * Hv], g_wvlo[Hv * Hv];
__device__ __nv_bfloat16 g_wohi[Hv * Hv], g_wolo[Hv * Hv];
__device__ __nv_bfloat16 g_qhi[Mv * Hv], g_qlo[Mv * Hv];
__device__ __nv_bfloat16 g_khi[Mv * Hv], g_klo[Mv * Hv];
__device__ float g_v [Mv * Hv];
__device__ float g_ao[Mv * Hv];
__device__ __nv_bfloat16 g_aohi[Mv * Hv], g_aolo[Mv * Hv];

__device__ __forceinline__ float elu1(float x) {
    return x > 0.f ? x + 1.f : __expf(x);
}

// Fast exp: FMA/ALU only (no MUFU).
__device__ __forceinline__ float fexp(float x) {
    x = fmaxf(x, -80.f);
    float t  = x * 1.44269504089f;
    float tb = t + 12582912.f;
    float fi = tb - 12582912.f;
    float f  = t - fi;
    int   i  = __float_as_int(tb) - 0x4B400000;
    float p  = 1.33335581e-3f;
    p = fmaf(p, f, 9.61812910e-3f);
    p = fmaf(p, f, 5.55041087e-2f);
    p = fmaf(p, f, 2.40226507e-1f);
    p = fmaf(p, f, 6.93147181e-1f);
    p = fmaf(p, f, 1.0f);
    return __int_as_float(__float_as_int(p) + (i << 23));
}

// ---------------------------------------------------------------------------
// helpers
// ---------------------------------------------------------------------------
__device__ __forceinline__ void splitb(float x, __nv_bfloat16& h, __nv_bfloat16& l) {
    h = __float2bfloat16(x);
    l = __float2bfloat16(x - __bfloat162float(h));
}
__device__ __forceinline__ uint32_t cvt_tf32(float x) {
    uint32_t r;
    asm("cvt.rna.tf32.f32 %0, %1;" : "=r"(r) : "f"(x));
    return r;
}
// bf16 mma m16n8k16
__device__ __forceinline__ void mma16(float* c, const uint32_t* a, uint32_t b0, uint32_t b1) {
    asm volatile(
        "mma.sync.aligned.m16n8k16.row.col.f32.bf16.bf16.f32 "
        "{%0,%1,%2,%3}, {%4,%5,%6,%7}, {%8,%9}, {%0,%1,%2,%3};"
        : "+f"(c[0]), "+f"(c[1]), "+f"(c[2]), "+f"(c[3])
        : "r"(a[0]), "r"(a[1]), "r"(a[2]), "r"(a[3]), "r"(b0), "r"(b1));
}
// tf32 mma m16n8k8 (PV path)
__device__ __forceinline__ void mma8(float* c, const uint32_t* a, uint32_t b0, uint32_t b1) {
    asm volatile(
        "mma.sync.aligned.m16n8k8.row.col.f32.tf32.tf32.f32 "
        "{%0,%1,%2,%3}, {%4,%5,%6,%7}, {%8,%9}, {%0,%1,%2,%3};"
        : "+f"(c[0]), "+f"(c[1]), "+f"(c[2]), "+f"(c[3])
        : "r"(a[0]), "r"(a[1]), "r"(a[2]), "r"(a[3]), "r"(b0), "r"(b1));
}
__device__ __forceinline__ uint32_t smem_u32(const void* p) {
    uint32_t a;
    asm("{ .reg .u64 t; cvta.to.shared.u64 t, %1; cvt.u32.u64 %0, t; }" : "=r"(a) : "l"(p));
    return a;
}
__device__ __forceinline__ void cp_async16(uint32_t sm, const void* g) {
    asm volatile("cp.async.cg.shared.global [%0], [%1], 16;" :: "r"(sm), "l"(g));
}
#define CP_COMMIT() asm volatile("cp.async.commit_group;" ::: "memory")
template <int N>
__device__ __forceinline__ void cp_wait() {
    asm volatile("cp.async.wait_group %0;" :: "n"(N) : "memory");
}

// smem swizzles (16B-block XOR by row) — conflict-free fragment LDS
__device__ __forceinline__ int sxh(int row, int col) {     // 32-half rows (proj tiles)
    return row * 32 + ((col & 7) | ((((col >> 3) ^ (row >> 1)) & 3) << 3));
}
__device__ __forceinline__ int s64(int row, int col) {     // 64-half rows (attn Q/K)
    return row * 64 + ((col & 7) | ((((col >> 3) ^ row) & 7) << 3));
}

// ---------------------------------------------------------------------------
// Prep: elementwise bf16 hi/lo split
// ---------------------------------------------------------------------------
__global__ void split_one(const float* __restrict__ src,
                          __nv_bfloat16* __restrict__ hi,
                          __nv_bfloat16* __restrict__ lo, int n)
{
    int i = (blockIdx.x * 256 + threadIdx.x) * 4;
    if (i >= n) return;
    float4 x = *reinterpret_cast<const float4*>(src + i);
    __nv_bfloat16 h0, l0, h1, l1, h2, l2, h3, l3;
    splitb(x.x, h0, l0); splitb(x.y, h1, l1);
    splitb(x.z, h2, l2); splitb(x.w, h3, l3);
    __nv_bfloat162 H0; H0.x = h0; H0.y = h1;
    __nv_bfloat162 H1; H1.x = h2; H1.y = h3;
    __nv_bfloat162 L0; L0.x = l0; L0.y = l1;
    __nv_bfloat162 L1; L1.x = l2; L1.y = l3;
    *reinterpret_cast<__nv_bfloat162*>(hi + i)     = H0;
    *reinterpret_cast<__nv_bfloat162*>(hi + i + 2) = H1;
    *reinterpret_cast<__nv_bfloat162*>(lo + i)     = L0;
    *reinterpret_cast<__nv_bfloat162*>(lo + i + 2) = L1;
}

// ---------------------------------------------------------------------------
// 3xBF16 GEMM body: C = A @ W^T, pre-split operands in gmem.
// Tile 128x128x32, 3-stage cp.async, zero in-loop conversions.
// OUT 0: elu+1, split -> bf16 hi/lo planes [B,NH,S,HD]
// OUT 1: fp32 [M,N] row-major
// OUT 2: fp32 [B,NH,S,HD]
// ---------------------------------------------------------------------------
#define BK 32
#define NKC (Hv / BK)
#define STG_H (4 * 128 * 32)            // halfs per stage
#define GEMM_SMEM (3 * STG_H * 2)       // 98304 B

template <int OUT>
__device__ __forceinline__ void gemm_bf16_body(
    const __nv_bfloat16* __restrict__ Ah, const __nv_bfloat16* __restrict__ Al,
    const __nv_bfloat16* __restrict__ Bh, const __nv_bfloat16* __restrict__ Bl,
    __nv_bfloat16* __restrict__ Chi, __nv_bfloat16* __restrict__ Clo,
    float* __restrict__ Cf,
    uint16_t* sm, int m0, int n0)
{
    const int tid  = threadIdx.x;
    const int w    = tid >> 5;
    const int lane = tid & 31;
    const int g    = lane >> 2;
    const int t    = lane & 3;
    const int wm   = (w & 3) * 32;
    const int wn   = (w >> 2) * 64;

    auto load_stage = [&](int c, int s) {
        const int k0 = c * BK;
        uint16_t* st = sm + s * STG_H;
#pragma unroll
        for (int i = 0; i < 8; i++) {
            int idx = tid + i * 256;
            int arr = idx >> 9;
            int rem = idx & 511;
            int row = rem >> 2, seg = rem & 3;
            const __nv_bfloat16* gp;
            if (arr == 0)      gp = Ah + (size_t)(m0 + row) * Hv;
            else if (arr == 1) gp = Al + (size_t)(m0 + row) * Hv;
            else if (arr == 2) gp = Bh + (size_t)(n0 + row) * Hv;
            else               gp = Bl + (size_t)(n0 + row) * Hv;
            int sc = ((seg ^ (row >> 1)) & 3) * 8;
            cp_async16(smem_u32(st + arr * 4096 + row * 32 + sc), gp + k0 + seg * 8);
        }
    };

    float acc[2][8][4];
#pragma unroll
    for (int i = 0; i < 2; i++)
#pragma unroll
        for (int j = 0; j < 8; j++)
#pragma unroll
            for (int r = 0; r < 4; r++) acc[i][j][r] = 0.f;

    load_stage(0, 0); CP_COMMIT();
    load_stage(1, 1); CP_COMMIT();

    for (int c = 0; c < NKC; c++) {
        cp_wait<1>();
        __syncthreads();
        if (c + 2 < NKC) load_stage(c + 2, (c + 2) % 3);
        CP_COMMIT();

        uint16_t* st  = sm + (c % 3) * STG_H;
        uint16_t* sAh = st;
        uint16_t* sAl = st + 4096;
        uint16_t* sBh = st + 8192;
        uint16_t* sBl = st + 12288;

#pragma unroll
        for (int kb = 0; kb < 2; kb++) {
            const int koff = kb * 16 + 2 * t;
            uint32_t ah[2][4], al[2][4];
#pragma unroll
            for (int i = 0; i < 2; i++) {
                const int r = wm + i * 16 + g;
                ah[i][0] = *reinterpret_cast<uint32_t*>(&sAh[sxh(r,     koff)]);
                ah[i][1] = *reinterpret_cast<uint32_t*>(&sAh[sxh(r + 8, koff)]);
                ah[i][2] = *reinterpret_cast<uint32_t*>(&sAh[sxh(r,     koff + 8)]);
                ah[i][3] = *reinterpret_cast<uint32_t*>(&sAh[sxh(r + 8, koff + 8)]);
                al[i][0] = *reinterpret_cast<uint32_t*>(&sAl[sxh(r,     koff)]);
                al[i][1] = *reinterpret_cast<uint32_t*>(&sAl[sxh(r + 8, koff)]);
                al[i][2] = *reinterpret_cast<uint32_t*>(&sAl[sxh(r,     koff + 8)]);
                al[i][3] = *reinterpret_cast<uint32_t*>(&sAl[sxh(r + 8, koff + 8)]);
            }
#pragma unroll
            for (int j = 0; j < 8; j++) {
                const int n = wn + j * 8 + g;
                uint32_t bh0 = *reinterpret_cast<uint32_t*>(&sBh[sxh(n, koff)]);
                uint32_t bh1 = *reinterpret_cast<uint32_t*>(&sBh[sxh(n, koff + 8)]);
                uint32_t bl0 = *reinterpret_cast<uint32_t*>(&sBl[sxh(n, koff)]);
                uint32_t bl1 = *reinterpret_cast<uint32_t*>(&sBl[sxh(n, koff + 8)]);
#pragma unroll
                for (int i = 0; i < 2; i++) {
                    mma16(acc[i][j], ah[i], bl0, bl1);
                    mma16(acc[i][j], al[i], bh0, bh1);
                    mma16(acc[i][j], ah[i], bh0, bh1);
                }
            }
        }
    }

#pragma unroll
    for (int i = 0; i < 2; i++) {
#pragma unroll
        for (int rr = 0; rr < 2; rr++) {
            const int m  = m0 + wm + i * 16 + g + rr * 8;
            const int bb = m >> 11;
            const int ss = m & (Sv - 1);
#pragma unroll
            for (int j = 0; j < 8; j++) {
                float x0 = acc[i][j][rr * 2 + 0];
                float x1 = acc[i][j][rr * 2 + 1];
                const int n = n0 + wn + j * 8 + 2 * t;
                if (OUT == 1) {
                    *reinterpret_cast<float2*>(&Cf[(size_t)m * Hv + n]) = make_float2(x0, x1);
                } else if (OUT == 2) {
                    const int hh = n >> 6, dd = n & 63;
                    *reinterpret_cast<float2*>(
                        &Cf[((size_t)(bb * NHv + hh) * Sv + ss) * HDv + dd]) = make_float2(x0, x1);
                } else {
                    x0 = elu1(x0); x1 = elu1(x1);
                    __nv_bfloat16 h0, l0, h1, l1;
                    splitb(x0, h0, l0);
                    splitb(x1, h1, l1);
                    const int hh = n >> 6, dd = n & 63;
                    const size_t o = ((size_t)(bb * NHv + hh) * Sv + ss) * HDv + dd;
                    __nv_bfloat162 H; H.x = h0; H.y = h1;
                    __nv_bfloat162 L; L.x = l0; L.y = l1;
                    *reinterpret_cast<__nv_bfloat162*>(&Chi[o]) = H;
                    *reinterpret_cast<__nv_bfloat162*>(&Clo[o]) = L;
                }
            }
        }
    }
}

__global__ __launch_bounds__(256) void proj_qkv()
{
    extern __shared__ char smraw[];
    uint16_t* sm = (uint16_t*)smraw;
    const int z  = blockIdx.z;
    const int m0 = blockIdx.y * 128, n0 = blockIdx.x * 128;
    if (z == 0)
        gemm_bf16_body<0>(g_ahi, g_alo, g_wqhi, g_wqlo, g_qhi, g_qlo, nullptr, sm, m0, n0);
    else if (z == 1)
        gemm_bf16_body<0>(g_ahi, g_alo, g_wkhi, g_wklo, g_khi, g_klo, nullptr, sm, m0, n0);
    else
        gemm_bf16_body<2>(g_ahi, g_alo, g_wvhi, g_wvlo, nullptr, nullptr, g_v, sm, m0, n0);
}

__global__ __launch_bounds__(256) void proj_o(float* __restrict__ out)
{
    extern __shared__ char smraw[];
    gemm_bf16_body<1>(g_aohi, g_aolo, g_wohi, g_wolo, nullptr, nullptr, out,
                      (uint16_t*)smraw, blockIdx.y * 128, blockIdx.x * 128);
}

// ---------------------------------------------------------------------------
// Flash attention: scores 3xBF16 (pre-split Q/K planes), PV single tf32.
// ---------------------------------------------------------------------------
#define VP 72
#define ATTN_SMEM ((2 * 128 * 64 + 2 * 64 * 64) * 2 + 64 * VP * 4 + 64 * 4)

__global__ __launch_bounds__(256, 2) void attn_mma(const int* __restrict__ mask)
{
    extern __shared__ char shraw[];
    uint16_t* Qh  = (uint16_t*)shraw;
    uint16_t* Ql  = Qh + 128 * 64;
    uint16_t* Kh  = Ql + 128 * 64;
    uint16_t* Kl  = Kh + 64 * 64;
    uint32_t* Vtf = (uint32_t*)(Kl + 64 * 64);
    int*      Ms  = (int*)(Vtf + 64 * VP);

    const int bb = blockIdx.z;
    const int hh = blockIdx.y;
    const int q0 = blockIdx.x * 128;

    const size_t hb = (size_t)(bb * NHv + hh) * Sv;
    const __nv_bfloat16* Qhg = g_qhi + (hb + q0) * HDv;
    const __nv_bfloat16* Qlg = g_qlo + (hb + q0) * HDv;
    const __nv_bfloat16* Khg = g_khi + hb * HDv;
    const __nv_bfloat16* Klg = g_klo + hb * HDv;
    const float*         Vg  = g_v   + hb * HDv;

    const int tid  = threadIdx.x;
    const int w    = tid >> 5;
    const int lane = tid & 31;
    const int g    = lane >> 2;
    const int t    = lane & 3;
    const int qb   = w * 16;

    // load Q tiles (hi/lo)
#pragma unroll
    for (int i = 0; i < 8; i++) {
        int idx = tid + i * 256;
        int row = idx >> 4, q4 = (idx & 15) * 4;
        int so = s64(row, q4);
        *reinterpret_cast<uint2*>(&Qh[so]) =
            *reinterpret_cast<const uint2*>(&Qhg[row * HDv + q4]);
        *reinterpret_cast<uint2*>(&Ql[so]) =
            *reinterpret_cast<const uint2*>(&Qlg[row * HDv + q4]);
    }

    float oacc[8][4];
#pragma unroll
    for (int j = 0; j < 8; j++)
#pragma unroll
        for (int r = 0; r < 4; r++) oacc[j][r] = 0.f;
    float m0r = -1e30f, m1r = -1e30f, l0r = 0.f, l1r = 0.f;

    for (int tk = 0; tk < Sv / 64; tk++) {
        const int k0 = tk * 64;
        __syncthreads();
#pragma unroll
        for (int i = 0; i < 4; i++) {
            int idx = tid + i * 256;
            int row = idx >> 4, q4 = (idx & 15) * 4;
            int so = s64(row, q4);
            *reinterpret_cast<uint2*>(&Kh[so]) =
                *reinterpret_cast<const uint2*>(&Khg[(size_t)(k0 + row) * HDv + q4]);
            *reinterpret_cast<uint2*>(&Kl[so]) =
                *reinterpret_cast<const uint2*>(&Klg[(size_t)(k0 + row) * HDv + q4]);
            float4 fv = *reinterpret_cast<const float4*>(&Vg[(size_t)(k0 + row) * HDv + q4]);
            uint4 vt;
            vt.x = cvt_tf32(fv.x); vt.y = cvt_tf32(fv.y);
            vt.z = cvt_tf32(fv.z); vt.w = cvt_tf32(fv.w);
            *reinterpret_cast<uint4*>(&Vtf[row * VP + q4]) = vt;
        }
        if (tid < 64) Ms[tid] = mask[bb * Sv + k0 + tid];
        __syncthreads();

        // ---- scores: S = Q @ K^T  (3xBF16) ----
        float sacc[8][4];
#pragma unroll
        for (int j = 0; j < 8; j++)
#pragma unroll
            for (int r = 0; r < 4; r++) sacc[j][r] = 0.f;

#pragma unroll
        for (int kb = 0; kb < 4; kb++) {
            const int koff = kb * 16 + 2 * t;
            uint32_t ah[4], al[4];
            ah[0] = *reinterpret_cast<uint32_t*>(&Qh[s64(qb + g,     koff)]);
            ah[1] = *reinterpret_cast<uint32_t*>(&Qh[s64(qb + g + 8, koff)]);
            ah[2] = *reinterpret_cast<uint32_t*>(&Qh[s64(qb + g,     koff + 8)]);
            ah[3] = *reinterpret_cast<uint32_t*>(&Qh[s64(qb + g + 8, koff + 8)]);
            al[0] = *reinterpret_cast<uint32_t*>(&Ql[s64(qb + g,     koff)]);
            al[1] = *reinterpret_cast<uint32_t*>(&Ql[s64(qb + g + 8, koff)]);
            al[2] = *reinterpret_cast<uint32_t*>(&Ql[s64(qb + g,     koff + 8)]);
            al[3] = *reinterpret_cast<uint32_t*>(&Ql[s64(qb + g + 8, koff + 8)]);
#pragma unroll
            for (int j = 0; j < 8; j++) {
                const int key = j * 8 + g;
                uint32_t bh0 = *reinterpret_cast<uint32_t*>(&Kh[s64(key, koff)]);
                uint32_t bh1 = *reinterpret_cast<uint32_t*>(&Kh[s64(key, koff + 8)]);
                uint32_t bl0 = *reinterpret_cast<uint32_t*>(&Kl[s64(key, koff)]);
                uint32_t bl1 = *reinterpret_cast<uint32_t*>(&Kl[s64(key, koff + 8)]);
                mma16(sacc[j], ah, bl0, bl1);
                mma16(sacc[j], al, bh0, bh1);
                mma16(sacc[j], ah, bh0, bh1);
            }
        }

        // ---- mask ----
#pragma unroll
        for (int j = 0; j < 8; j++) {
            if (Ms[j * 8 + 2 * t] == 0)     { sacc[j][0] = -1e30f; sacc[j][2] = -1e30f; }
            if (Ms[j * 8 + 2 * t + 1] == 0) { sacc[j][1] = -1e30f; sacc[j][3] = -1e30f; }
        }

        // ---- online softmax ----
        float mx0 = -1e30f, mx1 = -1e30f;
#pragma unroll
        for (int j = 0; j < 8; j++) {
            mx0 = fmaxf(mx0, fmaxf(sacc[j][0], sacc[j][1]));
            mx1 = fmaxf(mx1, fmaxf(sacc[j][2], sacc[j][3]));
        }
        mx0 = fmaxf(mx0, __shfl_xor_sync(0xffffffffu, mx0, 1));
        mx0 = fmaxf(mx0, __shfl_xor_sync(0xffffffffu, mx0, 2));
        mx1 = fmaxf(mx1, __shfl_xor_sync(0xffffffffu, mx1, 1));
        mx1 = fmaxf(mx1, __shfl_xor_sync(0xffffffffu, mx1, 2));

        const float mn0 = fmaxf(m0r, mx0);
        const float mn1 = fmaxf(m1r, mx1);
        const float a0  = fexp(m0r - mn0);
        const float a1  = fexp(m1r - mn1);
        m0r = mn0; m1r = mn1;

        float s0 = 0.f, s1 = 0.f;
#pragma unroll
        for (int j = 0; j < 8; j++) {
            sacc[j][0] = fexp(sacc[j][0] - mn0);
            sacc[j][1] = fexp(sacc[j][1] - mn0);
            sacc[j][2] = fexp(sacc[j][2] - mn1);
            sacc[j][3] = fexp(sacc[j][3] - mn1);
            s0 += sacc[j][0] + sacc[j][1];
            s1 += sacc[j][2] + sacc[j][3];
        }
        s0 += __shfl_xor_sync(0xffffffffu, s0, 1);
        s0 += __shfl_xor_sync(0xffffffffu, s0, 2);
        s1 += __shfl_xor_sync(0xffffffffu, s1, 1);
        s1 += __shfl_xor_sync(0xffffffffu, s1, 2);
        l0r = l0r * a0 + s0;
        l1r = l1r * a1 + s1;
#pragma unroll
        for (int j = 0; j < 8; j++) {
            oacc[j][0] *= a0; oacc[j][1] *= a0;
            oacc[j][2] *= a1; oacc[j][3] *= a1;
        }

        // ---- O += P @ V (single tf32; P frags via shuffle) ----
        const int src0 = (lane & 28) | (t >> 1);
        const int src1 = src0 | 2;
        const bool odd = (t & 1) != 0;
#pragma unroll
        for (int ks = 0; ks < 8; ks++) {
            float p0 = sacc[ks][0], p1 = sacc[ks][1];
            float p2 = sacc[ks][2], p3 = sacc[ks][3];
            float x0 = __shfl_sync(0xffffffffu, p0, src0);
            float x1 = __shfl_sync(0xffffffffu, p1, src0);
            float z0 = __shfl_sync(0xffffffffu, p2, src0);
            float z1 = __shfl_sync(0xffffffffu, p3, src0);
            float y0 = __shfl_sync(0xffffffffu, p0, src1);
            float y1 = __shfl_sync(0xffffffffu, p1, src1);
            float w0 = __shfl_sync(0xffffffffu, p2, src1);
            float w1 = __shfl_sync(0xffffffffu, p3, src1);
            uint32_t ap[4];
            ap[0] = cvt_tf32(odd ? x1 : x0);
            ap[1] = cvt_tf32(odd ? z1 : z0);
            ap[2] = cvt_tf32(odd ? y1 : y0);
            ap[3] = cvt_tf32(odd ? w1 : w0);
#pragma unroll
            for (int j = 0; j < 8; j++) {
                uint32_t b0 = Vtf[(ks * 8 + t) * VP + j * 8 + g];
                uint32_t b1 = Vtf[(ks * 8 + t + 4) * VP + j * 8 + g];
                mma8(oacc[j], ap, b0, b1);
            }
        }
    }

    // ---- normalize + write [B,S,H] (g_ao) ----
    const float i0 = 1.f / l0r;
    const float i1 = 1.f / l1r;
    const int r0 = q0 + qb + g;
    const int r1 = r0 + 8;
#pragma unroll
    for (int j = 0; j < 8; j++) {
        const int col = hh * 64 + j * 8 + 2 * t;
        *reinterpret_cast<float2*>(&g_ao[((size_t)bb * Sv + r0) * Hv + col]) =
            make_float2(oacc[j][0] * i0, oacc[j][1] * i0);
        *reinterpret_cast<float2*>(&g_ao[((size_t)bb * Sv + r1) * Hv + col]) =
            make_float2(oacc[j][2] * i1, oacc[j][3] * i1);
    }
}

// ---------------------------------------------------------------------------
extern "C" void kernel_launch(void* const* d_in, const int* in_sizes, int n_in,
                              void* d_out, int out_size)
{
    const float* hs   = (const float*)d_in[0];
    const int*   mask = (const int*)d_in[1];
    const float* Wq   = (const float*)d_in[2];
    const float* Wk   = (const float*)d_in[3];
    const float* Wv   = (const float*)d_in[4];
    const float* Wo   = (const float*)d_in[5];
    float*       out  = (float*)d_out;

    __nv_bfloat16 *ahi, *alo, *wqhi, *wqlo, *wkhi, *wklo, *wvhi, *wvlo, *wohi, *wolo, *aohi, *aolo;
    float* aop;
    cudaGetSymbolAddress((void**)&ahi,  g_ahi);  cudaGetSymbolAddress((void**)&alo,  g_alo);
    cudaGetSymbolAddress((void**)&wqhi, g_wqhi); cudaGetSymbolAddress((void**)&wqlo, g_wqlo);
    cudaGetSymbolAddress((void**)&wkhi, g_wkhi); cudaGetSymbolAddress((void**)&wklo, g_wklo);
    cudaGetSymbolAddress((void**)&wvhi, g_wvhi); cudaGetSymbolAddress((void**)&wvlo, g_wvlo);
    cudaGetSymbolAddress((void**)&wohi, g_wohi); cudaGetSymbolAddress((void**)&wolo, g_wolo);
    cudaGetSymbolAddress((void**)&aohi, g_aohi); cudaGetSymbolAddress((void**)&aolo, g_aolo);
    cudaGetSymbolAddress((void**)&aop,  g_ao);

    cudaFuncSetAttribute(proj_qkv, cudaFuncAttributeMaxDynamicSharedMemorySize, GEMM_SMEM);
    cudaFuncSetAttribute(proj_o,   cudaFuncAttributeMaxDynamicSharedMemorySize, GEMM_SMEM);
    cudaFuncSetAttribute(attn_mma, cudaFuncAttributeMaxDynamicSharedMemorySize, ATTN_SMEM);

    split_one<<<Mv * Hv / 1024, 256>>>(hs, ahi, alo, Mv * Hv);
    split_one<<<Hv * Hv / 1024, 256>>>(Wq, wqhi, wqlo, Hv * Hv);
    split_one<<<Hv * Hv / 1024, 256>>>(Wk, wkhi, wklo, Hv * Hv);
    split_one<<<Hv * Hv / 1024, 256>>>(Wv, wvhi, wvlo, Hv * Hv);
    split_one<<<Hv * Hv / 1024, 256>>>(Wo, wohi, wolo, Hv * Hv);

    proj_qkv<<<dim3(Hv / 128, Mv / 128, 3), 256, GEMM_SMEM>>>();

    attn_mma<<<dim3(Sv / 128, NHv, Bv), 256, ATTN_SMEM>>>(mask);

    split_one<<<Mv * Hv / 1024, 256>>>(aop, aohi, aolo, Mv * Hv);
    proj_o<<<dim3(Hv / 128, Mv / 128), 256, GEMM_SMEM>>>(out);
}